// round 1
// baseline (speedup 1.0000x reference)
#include <cuda_runtime.h>
#include <math.h>

#define BB       4096
#define SRC_LEN  128
#define IN_DIM   16
#define HH       64
#define SEQ_LEN  100
#define MEAN_DIM 4
#define COV_DIM  10

#define NG        4               // thread groups per CTA (64 threads each)
#define EPT       8               // batch elements per group
#define CTA_ELEMS (NG*EPT)        // 32
#define GRID1     (BB/CTA_ELEMS)  // 128
#define THREADS1  256

#define MEANS_OFF 0
#define COVS_OFF  (BB*SEQ_LEN*MEAN_DIM)   // 1638400

typedef unsigned long long ull;

// decoder output scratch [B][SEQ_LEN][IN_DIM]
__device__ __align__(16) float g_dec[BB*SEQ_LEN*IN_DIM];

// ---------------------------------------------------------------------------
// f32x2 packed helpers (Blackwell dual-fp32 FMA)
// ---------------------------------------------------------------------------
__device__ __forceinline__ ull pack2(float x, float y){
    ull r; asm("mov.b64 %0,{%1,%2};" : "=l"(r) : "f"(x), "f"(y)); return r;
}
__device__ __forceinline__ float2 unpack2(ull v){
    float2 r; asm("mov.b64 {%0,%1},%2;" : "=f"(r.x), "=f"(r.y) : "l"(v)); return r;
}
__device__ __forceinline__ ull fma2(ull a, ull b, ull c){
    ull d; asm("fma.rn.f32x2 %0,%1,%2,%3;" : "=l"(d) : "l"(a), "l"(b), "l"(c)); return d;
}

__device__ __forceinline__ float sigmoidf_(float x){
    return __fdividef(1.f, 1.f + __expf(-x));
}
__device__ __forceinline__ float tanhf_(float x){
    float u = __expf(-2.f * fabsf(x));
    float t = __fdividef(1.f - u, 1.f + u);
    return copysignf(t, x);
}

// ---------------------------------------------------------------------------
// SMEM layout for the sequential kernel  (~147 KB, dynamic)
// ---------------------------------------------------------------------------
struct SmemA {
    __align__(16) ull whh2[HH*192];            // Whh^T, duplicated lanes: [k][row] = (w,w)
    __align__(16) ull wih2[IN_DIM*192];        // Wih^T, duplicated lanes
    __align__(16) ull h2[NG][HH][EPT/2];       // h state: [g][k][e-pairs]
    __align__(16) ull xin2[NG][IN_DIM][EPT/2]; // current step input
    __align__(16) ull psum2[NG][4][IN_DIM][EPT/2]; // out-proj partials
    float bih[192], bhh[192];
    float outw[HH*IN_DIM];                     // out_W transposed [k][d]
    float outb[IN_DIM];
};

__device__ __forceinline__ float* h_rowf(SmemA& s, int g, int k){ return (float*)s.h2[g][k]; }
__device__ __forceinline__ float* xin_rowf(SmemA& s, int g, int d){ return (float*)s.xin2[g][d]; }
__device__ __forceinline__ float* psum_rowf(SmemA& s, int g, int ks, int d){ return (float*)s.psum2[g][ks][d]; }

__device__ __forceinline__ void load_gru_weights(SmemA& s,
        const float* __restrict__ Wih, const float* __restrict__ bih,
        const float* __restrict__ Whh, const float* __restrict__ bhh, int tid)
{
    for(int idx = tid; idx < HH*192; idx += THREADS1){
        int k = idx / 192, row = idx - k*192;
        float w = Whh[row*HH + k];
        s.whh2[idx] = pack2(w, w);
    }
    for(int idx = tid; idx < IN_DIM*192; idx += THREADS1){
        int k = idx / 192, row = idx - k*192;
        float w = Wih[row*IN_DIM + k];
        s.wih2[idx] = pack2(w, w);
    }
    for(int idx = tid; idx < 192; idx += THREADS1){
        s.bih[idx] = bih[idx];
        s.bhh[idx] = bhh[idx];
    }
}

// One GRU step for all NG*EPT elements. Thread (g,j) produces h[j] for its 8 elems.
// Contains 2 CTA barriers.
__device__ __forceinline__ void gru_step(SmemA& s, int g, int j)
{
    float br  = s.bih[j]      + s.bhh[j];
    float bz  = s.bih[64+j]   + s.bhh[64+j];
    float bni = s.bih[128+j];
    float bnh = s.bhh[128+j];

    ull ar0,ar1,ar2,ar3, az0,az1,az2,az3, an0,an1,an2,an3, ah0,ah1,ah2,ah3;
    ar0=ar1=ar2=ar3 = pack2(br, br);
    az0=az1=az2=az3 = pack2(bz, bz);
    an0=an1=an2=an3 = pack2(bni, bni);
    ah0=ah1=ah2=ah3 = pack2(bnh, bnh);

    // input contribution: gi = x @ Wih^T
    #pragma unroll
    for(int k = 0; k < IN_DIM; k++){
        const ulonglong2* xp = (const ulonglong2*)s.xin2[g][k];
        ulonglong2 xa = xp[0], xb = xp[1];
        const ull* w = &s.wih2[k*192];
        ull wr = w[j], wz = w[64+j], wn = w[128+j];
        ar0=fma2(xa.x,wr,ar0); ar1=fma2(xa.y,wr,ar1); ar2=fma2(xb.x,wr,ar2); ar3=fma2(xb.y,wr,ar3);
        az0=fma2(xa.x,wz,az0); az1=fma2(xa.y,wz,az1); az2=fma2(xb.x,wz,az2); az3=fma2(xb.y,wz,az3);
        an0=fma2(xa.x,wn,an0); an1=fma2(xa.y,wn,an1); an2=fma2(xb.x,wn,an2); an3=fma2(xb.y,wn,an3);
    }

    // recurrent contribution: gh = h @ Whh^T
    #pragma unroll 8
    for(int k = 0; k < HH; k++){
        const ulonglong2* hp = (const ulonglong2*)s.h2[g][k];
        ulonglong2 ha = hp[0], hb = hp[1];
        const ull* w = &s.whh2[k*192];
        ull wr = w[j], wz = w[64+j], wn = w[128+j];
        ar0=fma2(ha.x,wr,ar0); ar1=fma2(ha.y,wr,ar1); ar2=fma2(hb.x,wr,ar2); ar3=fma2(hb.y,wr,ar3);
        az0=fma2(ha.x,wz,az0); az1=fma2(ha.y,wz,az1); az2=fma2(hb.x,wz,az2); az3=fma2(hb.y,wz,az3);
        ah0=fma2(ha.x,wn,ah0); ah1=fma2(ha.y,wn,ah1); ah2=fma2(hb.x,wn,ah2); ah3=fma2(hb.y,wn,ah3);
    }

    float hold[EPT];
    {
        const float* hr = h_rowf(s, g, j);
        #pragma unroll
        for(int e = 0; e < EPT; e++) hold[e] = hr[e];
    }
    __syncthreads();   // all reads of h done before any write

    float rr[EPT], zz[EPT], ni[EPT], nh[EPT];
    { float2 t;
      t=unpack2(ar0); rr[0]=t.x; rr[1]=t.y;  t=unpack2(ar1); rr[2]=t.x; rr[3]=t.y;
      t=unpack2(ar2); rr[4]=t.x; rr[5]=t.y;  t=unpack2(ar3); rr[6]=t.x; rr[7]=t.y;
      t=unpack2(az0); zz[0]=t.x; zz[1]=t.y;  t=unpack2(az1); zz[2]=t.x; zz[3]=t.y;
      t=unpack2(az2); zz[4]=t.x; zz[5]=t.y;  t=unpack2(az3); zz[6]=t.x; zz[7]=t.y;
      t=unpack2(an0); ni[0]=t.x; ni[1]=t.y;  t=unpack2(an1); ni[2]=t.x; ni[3]=t.y;
      t=unpack2(an2); ni[4]=t.x; ni[5]=t.y;  t=unpack2(an3); ni[6]=t.x; ni[7]=t.y;
      t=unpack2(ah0); nh[0]=t.x; nh[1]=t.y;  t=unpack2(ah1); nh[2]=t.x; nh[3]=t.y;
      t=unpack2(ah2); nh[4]=t.x; nh[5]=t.y;  t=unpack2(ah3); nh[6]=t.x; nh[7]=t.y;
    }

    float* hw = h_rowf(s, g, j);
    #pragma unroll
    for(int e = 0; e < EPT; e++){
        float r = sigmoidf_(rr[e]);
        float z = sigmoidf_(zz[e]);
        float n = tanhf_(ni[e] + r * nh[e]);
        hw[e] = (1.f - z) * n + z * hold[e];
    }
    __syncthreads();   // writes visible before next consumer
}

// ---------------------------------------------------------------------------
// Kernel 1: encoder GRU (128 steps) + decoder GRU (100 steps, autoregressive)
// ---------------------------------------------------------------------------
__global__ void __launch_bounds__(THREADS1, 1) seq_kernel(
    const float* __restrict__ x,    const float* __restrict__ trg,
    const float* __restrict__ eWih, const float* __restrict__ ebih,
    const float* __restrict__ eWhh, const float* __restrict__ ebhh,
    const float* __restrict__ dWih, const float* __restrict__ dbih,
    const float* __restrict__ dWhh, const float* __restrict__ dbhh,
    const float* __restrict__ outW, const float* __restrict__ outb,
    const float* __restrict__ embW, const float* __restrict__ embb)
{
    extern __shared__ unsigned char smem_raw[];
    SmemA& s = *reinterpret_cast<SmemA*>(smem_raw);
    const int tid = threadIdx.x;
    const int g = tid >> 6;      // group 0..3
    const int j = tid & 63;      // h-row within group
    const int c = blockIdx.x;

    // ---- load encoder weights, zero h ----
    load_gru_weights(s, eWih, ebih, eWhh, ebhh, tid);
    for(int i = tid; i < NG*HH*EPT; i += THREADS1) ((float*)s.h2)[i] = 0.f;
    __syncthreads();

    // ---- encoder: 128 steps ----
    for(int t = 0; t < SRC_LEN; t++){
        for(int idx = tid; idx < NG*IN_DIM*EPT; idx += THREADS1){
            int gg = idx >> 7, r = idx & 127, e = r >> 4, d = r & 15;
            int b = c*CTA_ELEMS + gg*EPT + e;
            xin_rowf(s, gg, d)[e] = x[(b*SRC_LEN + t)*IN_DIM + d];
        }
        __syncthreads();
        gru_step(s, g, j);
    }

    // ---- switch to decoder weights ----
    load_gru_weights(s, dWih, dbih, dWhh, dbhh, tid);
    for(int idx = tid; idx < HH*IN_DIM; idx += THREADS1){
        int k = idx >> 4, d = idx & 15;
        s.outw[idx] = outW[d*HH + k];      // transposed [k][d]
    }
    if(tid < IN_DIM) s.outb[tid] = outb[tid];

    // ---- initial decoder input: emb(trg) ----
    for(int idx = tid; idx < NG*IN_DIM*EPT; idx += THREADS1){
        int gg = idx >> 7, r = idx & 127, e = r >> 4, d = r & 15;
        int b = c*CTA_ELEMS + gg*EPT + e;
        float a = embb[d];
        #pragma unroll
        for(int sx = 0; sx < 4; sx++) a += embW[d*4 + sx] * trg[b*4 + sx];
        xin_rowf(s, gg, d)[e] = a;
    }
    __syncthreads();

    // ---- decoder: 100 steps ----
    for(int t = 0; t < SEQ_LEN; t++){
        gru_step(s, g, j);

        // out projection partials: thread (d = j&15, ks = j>>4) covers 16 k's
        {
            int d = j & 15, ks = j >> 4;
            ull p0 = 0, p1 = 0, p2 = 0, p3 = 0;
            #pragma unroll
            for(int ki = 0; ki < 16; ki++){
                int k = ks*16 + ki;
                float w = s.outw[k*16 + d];
                ull wp = pack2(w, w);
                const ulonglong2* hp = (const ulonglong2*)s.h2[g][k];
                ulonglong2 ha = hp[0], hb = hp[1];
                p0 = fma2(ha.x, wp, p0); p1 = fma2(ha.y, wp, p1);
                p2 = fma2(hb.x, wp, p2); p3 = fma2(hb.y, wp, p3);
            }
            ull* pp = s.psum2[g][ks][d];
            pp[0] = p0; pp[1] = p1; pp[2] = p2; pp[3] = p3;
        }
        __syncthreads();

        // reduce partials -> o; feed back as next input; store dec_out
        if(j < IN_DIM){
            int d = j;
            #pragma unroll
            for(int e = 0; e < EPT; e++){
                float o = s.outb[d]
                        + psum_rowf(s, g, 0, d)[e] + psum_rowf(s, g, 1, d)[e]
                        + psum_rowf(s, g, 2, d)[e] + psum_rowf(s, g, 3, d)[e];
                xin_rowf(s, g, d)[e] = o;
                int b = c*CTA_ELEMS + g*EPT + e;
                g_dec[(b*SEQ_LEN + t)*IN_DIM + d] = o;
            }
        }
        __syncthreads();
    }
}

// ---------------------------------------------------------------------------
// Kernel 2: output heads (GELU-MLP x2), one (b,t) row per thread
// ---------------------------------------------------------------------------
__global__ void __launch_bounds__(256) heads_kernel(
    const float* __restrict__ mhW1, const float* __restrict__ mhb1,
    const float* __restrict__ mhW2, const float* __restrict__ mhb2,
    const float* __restrict__ chW1, const float* __restrict__ chb1,
    const float* __restrict__ chW2, const float* __restrict__ chb2,
    float* __restrict__ out)
{
    __shared__ float w1m[HH*IN_DIM], w1c[HH*IN_DIM];
    __shared__ float w2m[MEAN_DIM*HH], w2c[COV_DIM*HH];
    __shared__ float b1m[HH], b1c[HH], b2m[MEAN_DIM], b2c[COV_DIM];

    int tid = threadIdx.x;
    for(int i = tid; i < HH*IN_DIM; i += 256){ w1m[i] = mhW1[i]; w1c[i] = chW1[i]; }
    for(int i = tid; i < MEAN_DIM*HH; i += 256) w2m[i] = mhW2[i];
    for(int i = tid; i < COV_DIM*HH;  i += 256) w2c[i] = chW2[i];
    if(tid < HH){ b1m[tid] = mhb1[tid]; b1c[tid] = chb1[tid]; }
    if(tid < MEAN_DIM) b2m[tid] = mhb2[tid];
    if(tid < COV_DIM)  b2c[tid] = chb2[tid];
    __syncthreads();

    int row = blockIdx.x*256 + tid;      // 0 .. B*SEQ_LEN-1, grid sized exactly
    const float4* op = (const float4*)&g_dec[(size_t)row*IN_DIM];
    float4 o0 = op[0], o1 = op[1], o2 = op[2], o3 = op[3];
    float ov[16] = { o0.x,o0.y,o0.z,o0.w, o1.x,o1.y,o1.z,o1.w,
                     o2.x,o2.y,o2.z,o2.w, o3.x,o3.y,o3.z,o3.w };

    float am[MEAN_DIM], ac[COV_DIM];
    #pragma unroll
    for(int m = 0; m < MEAN_DIM; m++) am[m] = b2m[m];
    #pragma unroll
    for(int v = 0; v < COV_DIM; v++)  ac[v] = b2c[v];

    const float ISQRT2 = 0.70710678118654752f;
    #pragma unroll 4
    for(int u = 0; u < HH; u++){
        float s1 = b1m[u], s2 = b1c[u];
        #pragma unroll
        for(int d = 0; d < 16; d++){
            s1 += w1m[u*16 + d] * ov[d];
            s2 += w1c[u*16 + d] * ov[d];
        }
        float g1 = 0.5f * s1 * (1.f + erff(s1 * ISQRT2));
        float g2 = 0.5f * s2 * (1.f + erff(s2 * ISQRT2));
        #pragma unroll
        for(int m = 0; m < MEAN_DIM; m++) am[m] += g1 * w2m[m*HH + u];
        #pragma unroll
        for(int v = 0; v < COV_DIM; v++)  ac[v] += g2 * w2c[v*HH + u];
    }

    // clamp dims 2,3 of means to [-1, 1]
    am[2] = fminf(fmaxf(am[2], -1.f), 1.f);
    am[3] = fminf(fmaxf(am[3], -1.f), 1.f);

    #pragma unroll
    for(int m = 0; m < MEAN_DIM; m++) out[MEANS_OFF + (size_t)row*MEAN_DIM + m] = am[m];
    #pragma unroll
    for(int v = 0; v < COV_DIM; v++)  out[COVS_OFF + (size_t)row*COV_DIM + v] = ac[v];
}

// ---------------------------------------------------------------------------
extern "C" void kernel_launch(void* const* d_in, const int* in_sizes, int n_in,
                              void* d_out, int out_size)
{
    const float* x     = (const float*)d_in[0];
    const float* trg   = (const float*)d_in[1];
    const float* eWih  = (const float*)d_in[2];
    const float* ebih  = (const float*)d_in[3];
    const float* eWhh  = (const float*)d_in[4];
    const float* ebhh  = (const float*)d_in[5];
    const float* dWih  = (const float*)d_in[6];
    const float* dbih  = (const float*)d_in[7];
    const float* dWhh  = (const float*)d_in[8];
    const float* dbhh  = (const float*)d_in[9];
    const float* outW  = (const float*)d_in[10];
    const float* outb  = (const float*)d_in[11];
    const float* embW  = (const float*)d_in[12];
    const float* embb  = (const float*)d_in[13];
    const float* mhW1  = (const float*)d_in[14];
    const float* mhb1  = (const float*)d_in[15];
    const float* mhW2  = (const float*)d_in[16];
    const float* mhb2  = (const float*)d_in[17];
    const float* chW1  = (const float*)d_in[18];
    const float* chb1  = (const float*)d_in[19];
    const float* chW2  = (const float*)d_in[20];
    const float* chb2  = (const float*)d_in[21];

    cudaFuncSetAttribute(seq_kernel, cudaFuncAttributeMaxDynamicSharedMemorySize,
                         (int)sizeof(SmemA));

    seq_kernel<<<GRID1, THREADS1, sizeof(SmemA)>>>(
        x, trg, eWih, ebih, eWhh, ebhh, dWih, dbih, dWhh, dbhh,
        outW, outb, embW, embb);

    heads_kernel<<<(BB*SEQ_LEN)/256, 256>>>(
        mhW1, mhb1, mhW2, mhb2, chW1, chb1, chW2, chb2, (float*)d_out);
}